// round 16
// baseline (speedup 1.0000x reference)
#include <cuda_runtime.h>
#include <cuda_bf16.h>
#include <math.h>

typedef unsigned long long u64;

// ------------------ scratch (__device__ globals; no allocation) ------------------
__device__ __nv_bfloat16 g_a1h[4096 * 256 * 64];
__device__ __nv_bfloat16 g_a1l[4096 * 256 * 64];
__device__ __nv_bfloat16 g_wB2h[9 * 128 * 64];    // conv2 w [tap][co][ci]
__device__ __nv_bfloat16 g_wB2l[9 * 128 * 64];
__device__ __nv_bfloat16 g_a2h[4096 * 64 * 128];
__device__ __nv_bfloat16 g_a2l[4096 * 64 * 128];
__device__ __nv_bfloat16 g_wB3h[9 * 256 * 128];   // conv3 w [tap][co][ci]
__device__ __nv_bfloat16 g_wB3l[9 * 256 * 128];
__device__ float g_fea[4096 * 16 * 256];          // conv3 out fp32 (loss input)
__device__ __nv_bfloat16 g_feah[4096 * 16 * 256];
__device__ __nv_bfloat16 g_feal[4096 * 16 * 256];
__device__ __nv_bfloat16 g_cdh[1024 * 256];       // codes bf16 hi [code][k]
__device__ __nv_bfloat16 g_cdl[1024 * 256];
__device__ __nv_bfloat16 g_wbh[16 * 512 * 256];   // fc1w bf16 hi [pos][n][c]
__device__ __nv_bfloat16 g_wbl[16 * 512 * 256];
__device__ float g_P[16 * 1024 * 512];            // P[pos][code][n]
__device__ float g_h[4096 * 512];
__device__ int   g_eidx[65536];
__device__ float g_cn[1024];
__device__ int   g_hist[1024];
__device__ float g_losspart[256];

__device__ __forceinline__ float gelu_t(float x) {
    float x3 = x * x * x;
    float t = tanhf(0.7978845608028654f * (x + 0.044715f * x3));
    return 0.5f * x * (1.0f + t);
}

// ---- cp.async helpers ----
__device__ __forceinline__ void cpa16(void* smem_dst, const void* gmem_src) {
    unsigned d = (unsigned)__cvta_generic_to_shared(smem_dst);
    asm volatile("cp.async.ca.shared.global [%0], [%1], 16;" :: "r"(d), "l"(gmem_src));
}
__device__ __forceinline__ void cpa16z(void* smem_dst, const void* gmem_src, int srcbytes) {
    unsigned d = (unsigned)__cvta_generic_to_shared(smem_dst);
    asm volatile("cp.async.ca.shared.global [%0], [%1], 16, %2;" :: "r"(d), "l"(gmem_src), "r"(srcbytes));
}
__device__ __forceinline__ void cpa_commit() { asm volatile("cp.async.commit_group;"); }
__device__ __forceinline__ void cpa_wait0()  { asm volatile("cp.async.wait_group 0;" ::: "memory"); }
__device__ __forceinline__ void cpa_wait1()  { asm volatile("cp.async.wait_group 1;" ::: "memory"); }

// ---- bf16 HMMA + ldmatrix ----
__device__ __forceinline__ void hmma(float* c, const unsigned* a, const unsigned* b) {
    asm volatile(
        "mma.sync.aligned.m16n8k16.row.col.f32.bf16.bf16.f32 "
        "{%0,%1,%2,%3}, {%4,%5,%6,%7}, {%8,%9}, {%0,%1,%2,%3};\n"
        : "+f"(c[0]), "+f"(c[1]), "+f"(c[2]), "+f"(c[3])
        : "r"(a[0]), "r"(a[1]), "r"(a[2]), "r"(a[3]), "r"(b[0]), "r"(b[1]));
}
__device__ __forceinline__ void ldm_x4(unsigned* r, const void* p) {
    unsigned a = (unsigned)__cvta_generic_to_shared(p);
    asm volatile("ldmatrix.sync.aligned.m8n8.x4.shared.b16 {%0,%1,%2,%3}, [%4];"
        : "=r"(r[0]), "=r"(r[1]), "=r"(r[2]), "=r"(r[3]) : "r"(a));
}
__device__ __forceinline__ void split_bf(float v, __nv_bfloat16& h, __nv_bfloat16& l) {
    h = __float2bfloat16(v);
    l = __float2bfloat16(v - __bfloat162float(h));
}

// ---------- conv1: writes bf16 hi/lo directly ----------
__global__ __launch_bounds__(256) void conv1_k(const float* __restrict__ x,
                                               const float* __restrict__ w,
                                               const float* __restrict__ bias) {
    __shared__ float sw1[27][64];
    __shared__ float sb1[64];
    int tid = threadIdx.x, b = blockIdx.x;
    for (int i = tid; i < 1728; i += 256) { int co = i & 63, t = i >> 6; sw1[t][co] = w[co * 27 + t]; }
    if (tid < 64) sb1[tid] = bias[tid];
    __syncthreads();
    int oh = tid >> 4, ow = tid & 15;
    const float* xb = x + (size_t)b * 3072;
    float in[27];
#pragma unroll
    for (int c = 0; c < 3; c++)
#pragma unroll
        for (int kh = 0; kh < 3; kh++)
#pragma unroll
            for (int kw = 0; kw < 3; kw++) {
                int ih = oh * 2 + kh - 1, iw = ow * 2 + kw - 1;
                float v = 0.f;
                if ((unsigned)ih < 32u && (unsigned)iw < 32u) v = xb[(c * 32 + ih) * 32 + iw];
                in[(c * 3 + kh) * 3 + kw] = v;
            }
    size_t ob = ((size_t)b * 256 + tid) * 64;
#pragma unroll
    for (int cq = 0; cq < 16; cq++) {
        float a0 = sb1[cq * 4], a1 = sb1[cq * 4 + 1], a2 = sb1[cq * 4 + 2], a3 = sb1[cq * 4 + 3];
#pragma unroll
        for (int t = 0; t < 27; t++) {
            float4 wv = *(float4*)&sw1[t][cq * 4];
            a0 = fmaf(in[t], wv.x, a0); a1 = fmaf(in[t], wv.y, a1);
            a2 = fmaf(in[t], wv.z, a2); a3 = fmaf(in[t], wv.w, a3);
        }
        float vv[4] = {fmaxf(a0, 0.f), fmaxf(a1, 0.f), fmaxf(a2, 0.f), fmaxf(a3, 0.f)};
        __nv_bfloat16 h[4], lo[4];
#pragma unroll
        for (int i = 0; i < 4; i++) split_bf(vv[i], h[i], lo[i]);
        *(uint2*)&g_a1h[ob + cq * 4] = *(uint2*)h;
        *(uint2*)&g_a1l[ob + cq * 4] = *(uint2*)lo;
    }
}

// ---------- weight/code converters ----------
__global__ __launch_bounds__(256) void cvt_w2_k(const float* __restrict__ w) {
    int tap = blockIdx.x, tid = threadIdx.x;
    for (int i = tid; i < 8192; i += 256) {
        int co = i >> 6, ci = i & 63;
        float v = w[(size_t)co * 576 + ci * 9 + tap];
        __nv_bfloat16 h, l; split_bf(v, h, l);
        g_wB2h[tap * 8192 + i] = h;
        g_wB2l[tap * 8192 + i] = l;
    }
}
__global__ __launch_bounds__(256) void cvt_w3_k(const float* __restrict__ w) {
    int tap = blockIdx.x, tid = threadIdx.x;
    for (int i = tid; i < 32768; i += 256) {
        int co = i >> 7, ci = i & 127;
        float v = w[(size_t)co * 1152 + ci * 9 + tap];
        __nv_bfloat16 h, l; split_bf(v, h, l);
        g_wB3h[tap * 32768 + i] = h;
        g_wB3l[tap * 32768 + i] = l;
    }
}
__global__ __launch_bounds__(256) void cvt_cd_k(const float* __restrict__ c0,
                                                const float* __restrict__ c1) {
    int c = blockIdx.x;
    const float* cp = (c < 512) ? c0 + (size_t)c * 256 : c1 + (size_t)(c - 512) * 256;
    for (int k = threadIdx.x; k < 256; k += 256) {
        __nv_bfloat16 h, l; split_bf(cp[k], h, l);
        g_cdh[(size_t)c * 256 + k] = h;
        g_cdl[(size_t)c * 256 + k] = l;
    }
}
// fc1w [512n][4096c'] -> g_wbh/g_wbl [pos][n][256c] bf16 (c' = c*16+pos)
__global__ __launch_bounds__(256) void cvt_wb_k(const float* __restrict__ w) {
    __shared__ __nv_bfloat16 shh[4096], shl[4096];
    int n = blockIdx.x, tid = threadIdx.x;
    for (int i = tid; i < 4096; i += 256) {
        float v = w[(size_t)n * 4096 + i];
        __nv_bfloat16 h, l; split_bf(v, h, l);
        shh[i] = h; shl[i] = l;
    }
    __syncthreads();
    for (int i = tid; i < 4096; i += 256) {
        int pos = i >> 8, c = i & 255;
        size_t o = ((size_t)pos * 512 + n) * 256 + c;
        g_wbh[o] = shh[c * 16 + pos];
        g_wbl[o] = shl[c * 16 + pos];
    }
}

// ================= HMMA machinery =================
// smem: 4 tiles (Ah,Al,Bh,Bl), each [2buf][128 rows][40 bf16]; 81920B total
#define HMMA_STEP(cb, ks)                                                            \
    {                                                                                \
        unsigned ah[2][4], al[2][4], bh4[2][4], bl4[2][4];                           \
        _Pragma("unroll")                                                            \
        for (int mt = 0; mt < 2; mt++) {                                             \
            int roff = (mw + mt * 16 + rA) * 40 + (ks) * 16 + kA;                    \
            ldm_x4(ah[mt], base[0] + (cb) * 5120 + roff);                            \
            ldm_x4(al[mt], base[1] + (cb) * 5120 + roff);                            \
        }                                                                            \
        _Pragma("unroll")                                                            \
        for (int p = 0; p < 2; p++) {                                                \
            int noff = (nw + p * 16 + nB) * 40 + (ks) * 16 + kB;                     \
            ldm_x4(bh4[p], base[2] + (cb) * 5120 + noff);                            \
            ldm_x4(bl4[p], base[3] + (cb) * 5120 + noff);                            \
        }                                                                            \
        _Pragma("unroll")                                                            \
        for (int mt = 0; mt < 2; mt++)                                               \
            _Pragma("unroll")                                                        \
            for (int p = 0; p < 2; p++)                                              \
                _Pragma("unroll")                                                    \
                for (int hh = 0; hh < 2; hh++) {                                     \
                    hmma(acc[mt][p * 2 + hh], ah[mt], &bh4[p][hh * 2]);              \
                    hmma(acc[mt][p * 2 + hh], ah[mt], &bl4[p][hh * 2]);              \
                    hmma(acc[mt][p * 2 + hh], al[mt], &bh4[p][hh * 2]);              \
                }                                                                    \
    }

// ---------- conv2: 2 images/block, C[128row,128co], K=576 ----------
__global__ __launch_bounds__(512, 2) void conv2_k(const float* __restrict__ bias) {
    extern __shared__ __nv_bfloat16 smem_bf[];
    __nv_bfloat16* base[4] = {smem_bf, smem_bf + 10240, smem_bf + 20480, smem_bf + 30720};
    int tid = threadIdx.x;
    int b0 = blockIdx.x * 2;
    int lane = tid & 31, wrp = tid >> 5;
    int g = lane >> 2, t2 = lane & 3;
    int mw = (wrp & 3) * 32, nw = (wrp >> 2) * 32;
    int rA = (lane & 7) + ((lane >> 3) & 1) * 8, kA = (lane >> 4) * 8;
    int nB = (lane >> 4) * 8 + (lane & 7), kB = ((lane >> 3) & 1) * 8;
    float acc[2][4][4];
#pragma unroll
    for (int mt = 0; mt < 2; mt++)
#pragma unroll
        for (int nt = 0; nt < 4; nt++)
#pragma unroll
            for (int i = 0; i < 4; i++) acc[mt][nt][i] = 0.f;

    auto stage = [&](int ch, int buf) {
        int tap = ch >> 1, ci0 = (ch & 1) * 32;
        int kh = tap / 3, kw = tap - kh * 3;
#pragma unroll
        for (int l = 0; l < 4; l++) {
            int gi = tid + 512 * l;
            int arr = gi >> 9;
            int rem = gi & 511;
            int row = rem >> 2, q = rem & 3;
            __nv_bfloat16* dst = base[arr] + buf * 5120 + row * 40 + q * 8;
            if (arr < 2) {
                int img = row >> 6, pos = row & 63;
                int oh = pos >> 3, ow = pos & 7;
                int ih = oh * 2 + kh - 1, iw = ow * 2 + kw - 1;
                int ok = ((unsigned)ih < 16u && (unsigned)iw < 16u) ? 16 : 0;
                size_t si = ok ? ((((size_t)(b0 + img) * 256) + ih * 16 + iw) * 64 + ci0 + q * 8) : 0;
                cpa16z(dst, (arr ? g_a1l : g_a1h) + si, ok);
            } else {
                cpa16(dst, ((arr == 3) ? g_wB2l : g_wB2h) + (size_t)tap * 8192 + row * 64 + ci0 + q * 8);
            }
        }
        cpa_commit();
    };

    stage(0, 0);
    stage(1, 1);
    for (int ch = 0; ch < 18; ch++) {
        int cb = ch & 1;
        if (ch + 1 < 18) cpa_wait1(); else cpa_wait0();
        __syncthreads();
        HMMA_STEP(cb, 0)
        HMMA_STEP(cb, 1)
        __syncthreads();
        if (ch + 2 < 18) stage(ch + 2, cb);
    }
    float2 bb[4];
#pragma unroll
    for (int nt = 0; nt < 4; nt++) bb[nt] = *(const float2*)&bias[nw + nt * 8 + t2 * 2];
#pragma unroll
    for (int mt = 0; mt < 2; mt++) {
        int r0 = mw + mt * 16 + g, r1 = r0 + 8;
        size_t o0 = (((size_t)(b0 + (r0 >> 6)) * 64) + (r0 & 63)) * 128;
        size_t o1 = (((size_t)(b0 + (r1 >> 6)) * 64) + (r1 & 63)) * 128;
#pragma unroll
        for (int nt = 0; nt < 4; nt++) {
            int c0 = nw + nt * 8 + t2 * 2;
            float v00 = fmaxf(acc[mt][nt][0] + bb[nt].x, 0.f);
            float v01 = fmaxf(acc[mt][nt][1] + bb[nt].y, 0.f);
            float v10 = fmaxf(acc[mt][nt][2] + bb[nt].x, 0.f);
            float v11 = fmaxf(acc[mt][nt][3] + bb[nt].y, 0.f);
            __nv_bfloat162 h0, l0, h1, l1;
            split_bf(v00, h0.x, l0.x); split_bf(v01, h0.y, l0.y);
            split_bf(v10, h1.x, l1.x); split_bf(v11, h1.y, l1.y);
            *(__nv_bfloat162*)&g_a2h[o0 + c0] = h0;
            *(__nv_bfloat162*)&g_a2l[o0 + c0] = l0;
            *(__nv_bfloat162*)&g_a2h[o1 + c0] = h1;
            *(__nv_bfloat162*)&g_a2l[o1 + c0] = l1;
        }
    }
}

// ---------- conv3: 8 images/block x 128 co, K=1152 ----------
__global__ __launch_bounds__(512, 2) void conv3_k(const float* __restrict__ bias) {
    extern __shared__ __nv_bfloat16 smem_bf[];
    __nv_bfloat16* base[4] = {smem_bf, smem_bf + 10240, smem_bf + 20480, smem_bf + 30720};
    int tid = threadIdx.x;
    int b0 = blockIdx.x * 8;
    int cob = blockIdx.y * 128;
    int lane = tid & 31, wrp = tid >> 5;
    int g = lane >> 2, t2 = lane & 3;
    int mw = (wrp & 3) * 32, nw = (wrp >> 2) * 32;
    int rA = (lane & 7) + ((lane >> 3) & 1) * 8, kA = (lane >> 4) * 8;
    int nB = (lane >> 4) * 8 + (lane & 7), kB = ((lane >> 3) & 1) * 8;
    float acc[2][4][4];
#pragma unroll
    for (int mt = 0; mt < 2; mt++)
#pragma unroll
        for (int nt = 0; nt < 4; nt++)
#pragma unroll
            for (int i = 0; i < 4; i++) acc[mt][nt][i] = 0.f;

    auto stage = [&](int ch, int buf) {
        int tap = ch >> 2, ci0 = (ch & 3) * 32;
        int kh = tap / 3, kw = tap - kh * 3;
#pragma unroll
        for (int l = 0; l < 4; l++) {
            int gi = tid + 512 * l;
            int arr = gi >> 9;
            int rem = gi & 511;
            int row = rem >> 2, q = rem & 3;
            __nv_bfloat16* dst = base[arr] + buf * 5120 + row * 40 + q * 8;
            if (arr < 2) {
                int img = row >> 4, pos = row & 15;
                int oh = pos >> 2, ow = pos & 3;
                int ih = oh * 2 + kh - 1, iw = ow * 2 + kw - 1;
                int ok = ((unsigned)ih < 8u && (unsigned)iw < 8u) ? 16 : 0;
                size_t si = ok ? ((((size_t)(b0 + img) * 64) + ih * 8 + iw) * 128 + ci0 + q * 8) : 0;
                cpa16z(dst, (arr ? g_a2l : g_a2h) + si, ok);
            } else {
                cpa16(dst, ((arr == 3) ? g_wB3l : g_wB3h)
                           + (size_t)tap * 32768 + (cob + row) * 128 + ci0 + q * 8);
            }
        }
        cpa_commit();
    };

    stage(0, 0);
    stage(1, 1);
    for (int ch = 0; ch < 36; ch++) {
        int cb = ch & 1;
        if (ch + 1 < 36) cpa_wait1(); else cpa_wait0();
        __syncthreads();
        HMMA_STEP(cb, 0)
        HMMA_STEP(cb, 1)
        __syncthreads();
        if (ch + 2 < 36) stage(ch + 2, cb);
    }
    float2 bb[4];
#pragma unroll
    for (int nt = 0; nt < 4; nt++) bb[nt] = *(const float2*)&bias[cob + nw + nt * 8 + t2 * 2];
#pragma unroll
    for (int mt = 0; mt < 2; mt++) {
        int r0 = mw + mt * 16 + g, r1 = r0 + 8;
        size_t o0 = (((size_t)(b0 + (r0 >> 4)) * 16) + (r0 & 15)) * 256 + cob;
        size_t o1 = (((size_t)(b0 + (r1 >> 4)) * 16) + (r1 & 15)) * 256 + cob;
#pragma unroll
        for (int nt = 0; nt < 4; nt++) {
            int c0 = nw + nt * 8 + t2 * 2;
            float v00 = fmaxf(acc[mt][nt][0] + bb[nt].x, 0.f);
            float v01 = fmaxf(acc[mt][nt][1] + bb[nt].y, 0.f);
            float v10 = fmaxf(acc[mt][nt][2] + bb[nt].x, 0.f);
            float v11 = fmaxf(acc[mt][nt][3] + bb[nt].y, 0.f);
            *(float2*)&g_fea[o0 + c0] = make_float2(v00, v01);
            *(float2*)&g_fea[o1 + c0] = make_float2(v10, v11);
            __nv_bfloat162 h0, l0, h1, l1;
            split_bf(v00, h0.x, l0.x); split_bf(v01, h0.y, l0.y);
            split_bf(v10, h1.x, l1.x); split_bf(v11, h1.y, l1.y);
            *(__nv_bfloat162*)&g_feah[o0 + c0] = h0;
            *(__nv_bfloat162*)&g_feal[o0 + c0] = l0;
            *(__nv_bfloat162*)&g_feah[o1 + c0] = h1;
            *(__nv_bfloat162*)&g_feal[o1 + c0] = l1;
        }
    }
}

// ---------- code norms ----------
__global__ void codenorm_k(const float* __restrict__ c0, const float* __restrict__ c1) {
    int c = blockIdx.x * 256 + threadIdx.x;
    const float* cp = (c < 512) ? c0 + (size_t)c * 256 : c1 + (size_t)(c - 512) * 256;
    float s = 0.f;
    for (int k = 0; k < 256; k += 4) {
        float4 v = *(const float4*)&cp[k];
        s += v.x * v.x + v.y * v.y + v.z * v.z + v.w * v.w;
    }
    g_cn[c] = s;
}

// ---------- VQ: 128 rows/block x 128-code tiles, K=256 ----------
__global__ __launch_bounds__(512, 2) void vq_k(const int* __restrict__ idxp) {
    extern __shared__ __nv_bfloat16 smem_bf[];
    __nv_bfloat16* base[4] = {smem_bf, smem_bf + 10240, smem_bf + 20480, smem_bf + 30720};
    int tid = threadIdx.x;
    int rowbase = blockIdx.x * 128;
    int lane = tid & 31, wrp = tid >> 5;
    int g = lane >> 2, t2 = lane & 3;
    int mw = (wrp & 3) * 32, nw = (wrp >> 2) * 32;
    int rA = (lane & 7) + ((lane >> 3) & 1) * 8, kA = (lane >> 4) * 8;
    int nB = (lane >> 4) * 8 + (lane & 7), kB = ((lane >> 3) & 1) * 8;
    int Kc = (idxp[0] == 0) ? 512 : 1024;
    int total = (Kc >> 7) * 8;               // tile = cc>>3, kc = cc&7
    float bv[4]; int bi[4];
#pragma unroll
    for (int i = 0; i < 4; i++) { bv[i] = 1e30f; bi[i] = 0; }
    float acc[2][4][4];
#pragma unroll
    for (int mt = 0; mt < 2; mt++)
#pragma unroll
        for (int nt = 0; nt < 4; nt++)
#pragma unroll
            for (int i = 0; i < 4; i++) acc[mt][nt][i] = 0.f;

    auto stage = [&](int cc, int buf) {
        int tile = cc >> 3, kc = cc & 7;
#pragma unroll
        for (int l = 0; l < 4; l++) {
            int gi = tid + 512 * l;
            int arr = gi >> 9;
            int rem = gi & 511;
            int row = rem >> 2, q = rem & 3;
            __nv_bfloat16* dst = base[arr] + buf * 5120 + row * 40 + q * 8;
            const __nv_bfloat16* src;
            if (arr < 2)
                src = (arr ? g_feal : g_feah) + (size_t)(rowbase + row) * 256 + kc * 32 + q * 8;
            else
                src = ((arr == 3) ? g_cdl : g_cdh) + (size_t)(tile * 128 + row) * 256 + kc * 32 + q * 8;
            cpa16(dst, src);
        }
        cpa_commit();
    };

    stage(0, 0);
    stage(1, 1);
    for (int cc = 0; cc < total; cc++) {
        int cb = cc & 1;
        if (cc + 1 < total) cpa_wait1(); else cpa_wait0();
        __syncthreads();
        HMMA_STEP(cb, 0)
        HMMA_STEP(cb, 1)
        if ((cc & 7) == 7) {
            int tile = cc >> 3;
#pragma unroll
            for (int nt = 0; nt < 4; nt++) {
                int c0 = tile * 128 + nw + nt * 8 + t2 * 2;
                float cn0 = g_cn[c0], cn1 = g_cn[c0 + 1];
#pragma unroll
                for (int mt = 0; mt < 2; mt++) {
                    float d00 = cn0 - 2.f * acc[mt][nt][0];
                    float d01 = cn1 - 2.f * acc[mt][nt][1];
                    float d10 = cn0 - 2.f * acc[mt][nt][2];
                    float d11 = cn1 - 2.f * acc[mt][nt][3];
                    int b0i = mt * 2, b1i = mt * 2 + 1;
                    if (d00 < bv[b0i]) { bv[b0i] = d00; bi[b0i] = c0; }
                    if (d01 < bv[b0i]) { bv[b0i] = d01; bi[b0i] = c0 + 1; }
                    if (d10 < bv[b1i]) { bv[b1i] = d10; bi[b1i] = c0; }
                    if (d11 < bv[b1i]) { bv[b1i] = d11; bi[b1i] = c0 + 1; }
                }
            }
#pragma unroll
            for (int mt = 0; mt < 2; mt++)
#pragma unroll
                for (int nt = 0; nt < 4; nt++)
#pragma unroll
                    for (int i = 0; i < 4; i++) acc[mt][nt][i] = 0.f;
        }
        __syncthreads();
        if (cc + 2 < total) stage(cc + 2, cb);
    }
    __syncthreads();
    float (*sbv)[16] = (float(*)[16])smem_bf;
    int   (*sbi)[16] = (int(*)[16])(smem_bf + 4096);
    int qidx = (wrp >> 2) * 4 + t2;
#pragma unroll
    for (int mt = 0; mt < 2; mt++) {
        int r0 = mw + mt * 16 + g, r1 = r0 + 8;
        sbv[r0][qidx] = bv[mt * 2];     sbi[r0][qidx] = bi[mt * 2];
        sbv[r1][qidx] = bv[mt * 2 + 1]; sbi[r1][qidx] = bi[mt * 2 + 1];
    }
    __syncthreads();
    if (tid < 128) {
        float v = sbv[tid][0]; int ii = sbi[tid][0];
#pragma unroll
        for (int q = 1; q < 16; q++) {
            float v2 = sbv[tid][q]; int i2 = sbi[tid][q];
            if (v2 < v || (v2 == v && i2 < ii)) { v = v2; ii = i2; }
        }
        g_eidx[rowbase + tid] = ii;
    }
}

// ---------- ptab via HMMA: P[pos] = codes @ fc1w_pos^T ----------
__global__ __launch_bounds__(512, 2) void ptab_k() {
    extern __shared__ __nv_bfloat16 smem_bf[];
    __nv_bfloat16* base[4] = {smem_bf, smem_bf + 10240, smem_bf + 20480, smem_bf + 30720};
    int tid = threadIdx.x;
    int cbb = blockIdx.x * 128;
    int nbb = blockIdx.y * 128;
    int pos = blockIdx.z;
    int lane = tid & 31, wrp = tid >> 5;
    int g = lane >> 2, t2 = lane & 3;
    int mw = (wrp & 3) * 32, nw = (wrp >> 2) * 32;
    int rA = (lane & 7) + ((lane >> 3) & 1) * 8, kA = (lane >> 4) * 8;
    int nB = (lane >> 4) * 8 + (lane & 7), kB = ((lane >> 3) & 1) * 8;
    float acc[2][4][4];
#pragma unroll
    for (int mt = 0; mt < 2; mt++)
#pragma unroll
        for (int nt = 0; nt < 4; nt++)
#pragma unroll
            for (int i = 0; i < 4; i++) acc[mt][nt][i] = 0.f;

    auto stage = [&](int kc, int buf) {
#pragma unroll
        for (int l = 0; l < 4; l++) {
            int gi = tid + 512 * l;
            int arr = gi >> 9;
            int rem = gi & 511;
            int row = rem >> 2, q = rem & 3;
            __nv_bfloat16* dst = base[arr] + buf * 5120 + row * 40 + q * 8;
            const __nv_bfloat16* src;
            if (arr < 2)
                src = (arr ? g_cdl : g_cdh) + (size_t)(cbb + row) * 256 + kc * 32 + q * 8;
            else
                src = ((arr == 3) ? g_wbl : g_wbh)
                      + ((size_t)pos * 512 + nbb + row) * 256 + kc * 32 + q * 8;
            cpa16(dst, src);
        }
        cpa_commit();
    };

    stage(0, 0);
    stage(1, 1);
    for (int kc = 0; kc < 8; kc++) {
        int cb = kc & 1;
        if (kc + 1 < 8) cpa_wait1(); else cpa_wait0();
        __syncthreads();
        HMMA_STEP(cb, 0)
        HMMA_STEP(cb, 1)
        __syncthreads();
        if (kc + 2 < 8) stage(kc + 2, cb);
    }
#pragma unroll
    for (int mt = 0; mt < 2; mt++) {
        int r0 = mw + mt * 16 + g, r1 = r0 + 8;
        size_t o0 = ((size_t)pos * 1024 + cbb + r0) * 512 + nbb;
        size_t o1 = ((size_t)pos * 1024 + cbb + r1) * 512 + nbb;
#pragma unroll
        for (int nt = 0; nt < 4; nt++) {
            int c0 = nw + nt * 8 + t2 * 2;
            *(float2*)&g_P[o0 + c0] = make_float2(acc[mt][nt][0], acc[mt][nt][1]);
            *(float2*)&g_P[o1 + c0] = make_float2(acc[mt][nt][2], acc[mt][nt][3]);
        }
    }
}

__global__ void zero_hist_k() { g_hist[threadIdx.x] = 0; }

// ---------- loss partials + histogram ----------
__global__ void loss_hist_k(const float* __restrict__ c0, const float* __restrict__ c1) {
    __shared__ float red[256];
    int row = blockIdx.x * 256 + threadIdx.x;
    int e = g_eidx[row];
    atomicAdd(&g_hist[e], 1);
    const float* cp = (e < 512) ? c0 + (size_t)e * 256 : c1 + (size_t)(e - 512) * 256;
    const float* f = g_fea + (size_t)row * 256;
    float s = 0.f;
    for (int k = 0; k < 256; k += 4) {
        float4 q = *(const float4*)&cp[k];
        float4 fv = *(const float4*)&f[k];
        float a = q.x - fv.x, b = q.y - fv.y, c = q.z - fv.z, d = q.w - fv.w;
        s += a * a + b * b + c * c + d * d;
    }
    red[threadIdx.x] = s;
    __syncthreads();
    for (int st = 128; st; st >>= 1) {
        if (threadIdx.x < st) red[threadIdx.x] += red[threadIdx.x + st];
        __syncthreads();
    }
    if (threadIdx.x == 0) g_losspart[blockIdx.x] = red[0];
}

// ---------- h = gelu(sum_pos P + b1) ----------
__global__ __launch_bounds__(512) void hgs_k(const float* __restrict__ fb) {
    __shared__ int se[16];
    int b = blockIdx.x, tid = threadIdx.x;
    if (tid < 16) se[tid] = g_eidx[b * 16 + tid];
    __syncthreads();
    float acc = fb[tid];
#pragma unroll
    for (int p = 0; p < 16; p++) acc += g_P[((size_t)p * 1024 + se[p]) * 512 + tid];
    g_h[(size_t)b * 512 + tid] = gelu_t(acc);
}

// ---------- fc2 ----------
__global__ __launch_bounds__(256) void fc2_k(const float* __restrict__ w,
                                             const float* __restrict__ bias,
                                             float* __restrict__ out) {
    __shared__ float sw[10][512];
    __shared__ float sb[10];
    int tid = threadIdx.x;
    for (int i = tid; i < 5120; i += 256) sw[i >> 9][i & 511] = w[i];
    if (tid < 10) sb[tid] = bias[tid];
    __syncthreads();
    int warp = tid >> 5, lane = tid & 31;
    int bimg = blockIdx.x * 8 + warp;
    const float* hr = g_h + (size_t)bimg * 512;
    float acc[10];
#pragma unroll
    for (int m = 0; m < 10; m++) acc[m] = 0.f;
    for (int k = 0; k < 16; k++) {
        float hv = hr[lane + 32 * k];
#pragma unroll
        for (int m = 0; m < 10; m++) acc[m] = fmaf(hv, sw[m][lane + 32 * k], acc[m]);
    }
#pragma unroll
    for (int off = 16; off; off >>= 1)
#pragma unroll
        for (int m = 0; m < 10; m++) acc[m] += __shfl_xor_sync(0xFFFFFFFFu, acc[m], off);
    if (lane < 10) out[(size_t)bimg * 10 + lane] = acc[lane] + sb[lane];
}

// ---------- loss + perplexity ----------
__global__ void losspp_k(float* __restrict__ dout, int osz) {
    __shared__ float red[256];
    int tid = threadIdx.x;
    red[tid] = g_losspart[tid];
    __syncthreads();
    for (int st = 128; st; st >>= 1) {
        if (tid < st) red[tid] += red[tid + st];
        __syncthreads();
    }
    float loss = 1.25f * red[0] / 16777216.0f;
    __syncthreads();
    float s = 0.f;
    for (int i = tid; i < 1024; i += 256) {
        float p = (float)g_hist[i] / 65536.0f;
        if (p > 0.f) s += p * logf(p + 1e-10f);
    }
    red[tid] = s;
    __syncthreads();
    for (int st = 128; st; st >>= 1) {
        if (tid < st) red[tid] += red[tid + st];
        __syncthreads();
    }
    if (tid == 0) { dout[osz - 2] = loss; dout[osz - 1] = expf(-red[0]); }
}

extern "C" void kernel_launch(void* const* d_in, const int* in_sizes, int n_in,
                              void* d_out, int out_size) {
    const float* x     = (const float*)d_in[0];
    const float* w1    = (const float*)d_in[1];
    const float* b1    = (const float*)d_in[2];
    const float* w2    = (const float*)d_in[3];
    const float* b2    = (const float*)d_in[4];
    const float* w3    = (const float*)d_in[5];
    const float* b3    = (const float*)d_in[6];
    const float* code0 = (const float*)d_in[7];
    const float* code1 = (const float*)d_in[8];
    const float* fc1w  = (const float*)d_in[9];
    const float* fc1b  = (const float*)d_in[10];
    const float* fc2w  = (const float*)d_in[11];
    const float* fc2b  = (const float*)d_in[12];
    const int*   idxp  = (const int*)d_in[13];
    float* out = (float*)d_out;

    cudaFuncSetAttribute(conv2_k, cudaFuncAttributeMaxDynamicSharedMemorySize, 81920);
    cudaFuncSetAttribute(conv3_k, cudaFuncAttributeMaxDynamicSharedMemorySize, 81920);
    cudaFuncSetAttribute(vq_k,    cudaFuncAttributeMaxDynamicSharedMemorySize, 81920);
    cudaFuncSetAttribute(ptab_k,  cudaFuncAttributeMaxDynamicSharedMemorySize, 81920);

    // conv2_k stays at our launch #3 (ncu -s 5 lands there after 2 harness launches).
    conv1_k<<<4096, 256>>>(x, w1, b1);                    // 0
    cvt_w2_k<<<9, 256>>>(w2);                             // 1
    cvt_w3_k<<<9, 256>>>(w3);                             // 2
    conv2_k<<<2048, 512, 81920>>>(b2);                    // 3
    conv3_k<<<dim3(512, 2), 512, 81920>>>(b3);            // 4
    cvt_cd_k<<<1024, 256>>>(code0, code1);                // 5
    codenorm_k<<<4, 256>>>(code0, code1);                 // 6
    vq_k<<<512, 512, 81920>>>(idxp);                      // 7
    zero_hist_k<<<1, 1024>>>();                           // 8
    loss_hist_k<<<256, 256>>>(code0, code1);              // 9
    cvt_wb_k<<<512, 256>>>(fc1w);                         // 10
    ptab_k<<<dim3(8, 4, 16), 512, 81920>>>();             // 11
    hgs_k<<<4096, 512>>>(fc1b);                           // 12
    fc2_k<<<512, 256>>>(fc2w, fc2b, out);                 // 13
    losspp_k<<<1, 256>>>(out, out_size);                  // 14
}

// round 17
// speedup vs baseline: 1.0191x; 1.0191x over previous
#include <cuda_runtime.h>
#include <cuda_bf16.h>
#include <math.h>

typedef unsigned long long u64;

// ------------------ scratch (__device__ globals; no allocation) ------------------
__device__ __nv_bfloat16 g_a1h[4096 * 256 * 64];
__device__ __nv_bfloat16 g_a1l[4096 * 256 * 64];
__device__ __nv_bfloat16 g_wB2h[9 * 128 * 64];    // conv2 w [tap][co][ci]
__device__ __nv_bfloat16 g_wB2l[9 * 128 * 64];
__device__ __nv_bfloat16 g_a2h[4096 * 64 * 128];
__device__ __nv_bfloat16 g_a2l[4096 * 64 * 128];
__device__ __nv_bfloat16 g_wB3h[9 * 256 * 128];   // conv3 w [tap][co][ci]
__device__ __nv_bfloat16 g_wB3l[9 * 256 * 128];
__device__ float g_fea[4096 * 16 * 256];          // conv3 out fp32 (loss input)
__device__ __nv_bfloat16 g_feah[4096 * 16 * 256];
__device__ __nv_bfloat16 g_feal[4096 * 16 * 256];
__device__ __nv_bfloat16 g_cdh[1024 * 256];       // codes bf16 hi [code][k]
__device__ __nv_bfloat16 g_cdl[1024 * 256];
__device__ __nv_bfloat16 g_wbh[16 * 512 * 256];   // fc1w bf16 hi [pos][n][c]
__device__ __nv_bfloat16 g_wbl[16 * 512 * 256];
__device__ float g_P[16 * 1024 * 512];            // P[pos][code][n]
__device__ float g_h[4096 * 512];
__device__ int   g_eidx[65536];
__device__ float g_cn[1024];
__device__ int   g_hist[1024];
__device__ float g_losspart[256];

__device__ __forceinline__ float gelu_t(float x) {
    float x3 = x * x * x;
    float t = tanhf(0.7978845608028654f * (x + 0.044715f * x3));
    return 0.5f * x * (1.0f + t);
}

// ---- cp.async helpers (.cg: bypass L1, keep staging off the L1tex pipe) ----
__device__ __forceinline__ void cpa16(void* smem_dst, const void* gmem_src) {
    unsigned d = (unsigned)__cvta_generic_to_shared(smem_dst);
    asm volatile("cp.async.cg.shared.global [%0], [%1], 16;" :: "r"(d), "l"(gmem_src));
}
__device__ __forceinline__ void cpa16z(void* smem_dst, const void* gmem_src, int srcbytes) {
    unsigned d = (unsigned)__cvta_generic_to_shared(smem_dst);
    asm volatile("cp.async.cg.shared.global [%0], [%1], 16, %2;" :: "r"(d), "l"(gmem_src), "r"(srcbytes));
}
__device__ __forceinline__ void cpa_commit() { asm volatile("cp.async.commit_group;"); }
__device__ __forceinline__ void cpa_wait0()  { asm volatile("cp.async.wait_group 0;" ::: "memory"); }

// ---- bf16 HMMA + ldmatrix ----
__device__ __forceinline__ void hmma(float* c, const unsigned* a, const unsigned* b) {
    asm volatile(
        "mma.sync.aligned.m16n8k16.row.col.f32.bf16.bf16.f32 "
        "{%0,%1,%2,%3}, {%4,%5,%6,%7}, {%8,%9}, {%0,%1,%2,%3};\n"
        : "+f"(c[0]), "+f"(c[1]), "+f"(c[2]), "+f"(c[3])
        : "r"(a[0]), "r"(a[1]), "r"(a[2]), "r"(a[3]), "r"(b[0]), "r"(b[1]));
}
__device__ __forceinline__ void ldm_x4(unsigned* r, const void* p) {
    unsigned a = (unsigned)__cvta_generic_to_shared(p);
    asm volatile("ldmatrix.sync.aligned.m8n8.x4.shared.b16 {%0,%1,%2,%3}, [%4];"
        : "=r"(r[0]), "=r"(r[1]), "=r"(r[2]), "=r"(r[3]) : "r"(a));
}
__device__ __forceinline__ void split_bf(float v, __nv_bfloat16& h, __nv_bfloat16& l) {
    h = __float2bfloat16(v);
    l = __float2bfloat16(v - __bfloat162float(h));
}

// ---------- conv1: writes bf16 hi/lo directly ----------
__global__ __launch_bounds__(256) void conv1_k(const float* __restrict__ x,
                                               const float* __restrict__ w,
                                               const float* __restrict__ bias) {
    __shared__ float sw1[27][64];
    __shared__ float sb1[64];
    int tid = threadIdx.x, b = blockIdx.x;
    for (int i = tid; i < 1728; i += 256) { int co = i & 63, t = i >> 6; sw1[t][co] = w[co * 27 + t]; }
    if (tid < 64) sb1[tid] = bias[tid];
    __syncthreads();
    int oh = tid >> 4, ow = tid & 15;
    const float* xb = x + (size_t)b * 3072;
    float in[27];
#pragma unroll
    for (int c = 0; c < 3; c++)
#pragma unroll
        for (int kh = 0; kh < 3; kh++)
#pragma unroll
            for (int kw = 0; kw < 3; kw++) {
                int ih = oh * 2 + kh - 1, iw = ow * 2 + kw - 1;
                float v = 0.f;
                if ((unsigned)ih < 32u && (unsigned)iw < 32u) v = xb[(c * 32 + ih) * 32 + iw];
                in[(c * 3 + kh) * 3 + kw] = v;
            }
    size_t ob = ((size_t)b * 256 + tid) * 64;
#pragma unroll
    for (int cq = 0; cq < 16; cq++) {
        float a0 = sb1[cq * 4], a1 = sb1[cq * 4 + 1], a2 = sb1[cq * 4 + 2], a3 = sb1[cq * 4 + 3];
#pragma unroll
        for (int t = 0; t < 27; t++) {
            float4 wv = *(float4*)&sw1[t][cq * 4];
            a0 = fmaf(in[t], wv.x, a0); a1 = fmaf(in[t], wv.y, a1);
            a2 = fmaf(in[t], wv.z, a2); a3 = fmaf(in[t], wv.w, a3);
        }
        float vv[4] = {fmaxf(a0, 0.f), fmaxf(a1, 0.f), fmaxf(a2, 0.f), fmaxf(a3, 0.f)};
        __nv_bfloat16 h[4], lo[4];
#pragma unroll
        for (int i = 0; i < 4; i++) split_bf(vv[i], h[i], lo[i]);
        *(uint2*)&g_a1h[ob + cq * 4] = *(uint2*)h;
        *(uint2*)&g_a1l[ob + cq * 4] = *(uint2*)lo;
    }
}

// ---------- weight/code converters ----------
__global__ __launch_bounds__(256) void cvt_w2_k(const float* __restrict__ w) {
    int tap = blockIdx.x, tid = threadIdx.x;
    for (int i = tid; i < 8192; i += 256) {
        int co = i >> 6, ci = i & 63;
        float v = w[(size_t)co * 576 + ci * 9 + tap];
        __nv_bfloat16 h, l; split_bf(v, h, l);
        g_wB2h[tap * 8192 + i] = h;
        g_wB2l[tap * 8192 + i] = l;
    }
}
__global__ __launch_bounds__(256) void cvt_w3_k(const float* __restrict__ w) {
    int tap = blockIdx.x, tid = threadIdx.x;
    for (int i = tid; i < 32768; i += 256) {
        int co = i >> 7, ci = i & 127;
        float v = w[(size_t)co * 1152 + ci * 9 + tap];
        __nv_bfloat16 h, l; split_bf(v, h, l);
        g_wB3h[tap * 32768 + i] = h;
        g_wB3l[tap * 32768 + i] = l;
    }
}
__global__ __launch_bounds__(256) void cvt_cd_k(const float* __restrict__ c0,
                                                const float* __restrict__ c1) {
    int c = blockIdx.x;
    const float* cp = (c < 512) ? c0 + (size_t)c * 256 : c1 + (size_t)(c - 512) * 256;
    for (int k = threadIdx.x; k < 256; k += 256) {
        __nv_bfloat16 h, l; split_bf(cp[k], h, l);
        g_cdh[(size_t)c * 256 + k] = h;
        g_cdl[(size_t)c * 256 + k] = l;
    }
}
// fc1w [512n][4096c'] -> g_wbh/g_wbl [pos][n][256c] bf16 (c' = c*16+pos)
__global__ __launch_bounds__(256) void cvt_wb_k(const float* __restrict__ w) {
    __shared__ __nv_bfloat16 shh[4096], shl[4096];
    int n = blockIdx.x, tid = threadIdx.x;
    for (int i = tid; i < 4096; i += 256) {
        float v = w[(size_t)n * 4096 + i];
        __nv_bfloat16 h, l; split_bf(v, h, l);
        shh[i] = h; shl[i] = l;
    }
    __syncthreads();
    for (int i = tid; i < 4096; i += 256) {
        int pos = i >> 8, c = i & 255;
        size_t o = ((size_t)pos * 512 + n) * 256 + c;
        g_wbh[o] = shh[c * 16 + pos];
        g_wbl[o] = shl[c * 16 + pos];
    }
}

// ================= HMMA machinery =================
// smem: 4 tiles (Ah,Al,Bh,Bl), each [2buf][128 rows][40 bf16]; 81920B total
#define HMMA_STEP(cb, ks)                                                            \
    {                                                                                \
        unsigned ah[2][4], al[2][4], bh4[2][4], bl4[2][4];                           \
        _Pragma("unroll")                                                            \
        for (int mt = 0; mt < 2; mt++) {                                             \
            int roff = (mw + mt * 16 + rA) * 40 + (ks) * 16 + kA;                    \
            ldm_x4(ah[mt], base[0] + (cb) * 5120 + roff);                            \
            ldm_x4(al[mt], base[1] + (cb) * 5120 + roff);                            \
        }                                                                            \
        _Pragma("unroll")                                                            \
        for (int p = 0; p < 2; p++) {                                                \
            int noff = (nw + p * 16 + nB) * 40 + (ks) * 16 + kB;                     \
            ldm_x4(bh4[p], base[2] + (cb) * 5120 + noff);                            \
            ldm_x4(bl4[p], base[3] + (cb) * 5120 + noff);                            \
        }                                                                            \
        _Pragma("unroll")                                                            \
        for (int mt = 0; mt < 2; mt++)                                               \
            _Pragma("unroll")                                                        \
            for (int p = 0; p < 2; p++)                                              \
                _Pragma("unroll")                                                    \
                for (int hh = 0; hh < 2; hh++) {                                     \
                    hmma(acc[mt][p * 2 + hh], ah[mt], &bh4[p][hh * 2]);              \
                    hmma(acc[mt][p * 2 + hh], ah[mt], &bl4[p][hh * 2]);              \
                    hmma(acc[mt][p * 2 + hh], al[mt], &bh4[p][hh * 2]);              \
                }                                                                    \
    }

// ---------- conv2: 2 images/block, C[128row,128co], K=576 ----------
__global__ __launch_bounds__(512, 2) void conv2_k(const float* __restrict__ bias) {
    extern __shared__ __nv_bfloat16 smem_bf[];
    __nv_bfloat16* base[4] = {smem_bf, smem_bf + 10240, smem_bf + 20480, smem_bf + 30720};
    int tid = threadIdx.x;
    int b0 = blockIdx.x * 2;
    int lane = tid & 31, wrp = tid >> 5;
    int g = lane >> 2, t2 = lane & 3;
    int mw = (wrp & 3) * 32, nw = (wrp >> 2) * 32;
    int rA = (lane & 7) + ((lane >> 3) & 1) * 8, kA = (lane >> 4) * 8;
    int nB = (lane >> 4) * 8 + (lane & 7), kB = ((lane >> 3) & 1) * 8;
    float acc[2][4][4];
#pragma unroll
    for (int mt = 0; mt < 2; mt++)
#pragma unroll
        for (int nt = 0; nt < 4; nt++)
#pragma unroll
            for (int i = 0; i < 4; i++) acc[mt][nt][i] = 0.f;

    auto stage = [&](int ch, int buf) {
        int tap = ch >> 1, ci0 = (ch & 1) * 32;
        int kh = tap / 3, kw = tap - kh * 3;
#pragma unroll
        for (int l = 0; l < 4; l++) {
            int gi = tid + 512 * l;
            int arr = gi >> 9;
            int rem = gi & 511;
            int row = rem >> 2, q = rem & 3;
            __nv_bfloat16* dst = base[arr] + buf * 5120 + row * 40 + q * 8;
            if (arr < 2) {
                int img = row >> 6, pos = row & 63;
                int oh = pos >> 3, ow = pos & 7;
                int ih = oh * 2 + kh - 1, iw = ow * 2 + kw - 1;
                int ok = ((unsigned)ih < 16u && (unsigned)iw < 16u) ? 16 : 0;
                size_t si = ok ? ((((size_t)(b0 + img) * 256) + ih * 16 + iw) * 64 + ci0 + q * 8) : 0;
                cpa16z(dst, (arr ? g_a1l : g_a1h) + si, ok);
            } else {
                cpa16(dst, ((arr == 3) ? g_wB2l : g_wB2h) + (size_t)tap * 8192 + row * 64 + ci0 + q * 8);
            }
        }
        cpa_commit();
    };

    stage(0, 0);
    for (int ch = 0; ch < 18; ch++) {
        int cb = ch & 1;
        cpa_wait0();
        __syncthreads();
        if (ch + 1 < 18) stage(ch + 1, cb ^ 1);
        HMMA_STEP(cb, 0)
        HMMA_STEP(cb, 1)
    }
    float2 bb[4];
#pragma unroll
    for (int nt = 0; nt < 4; nt++) bb[nt] = *(const float2*)&bias[nw + nt * 8 + t2 * 2];
#pragma unroll
    for (int mt = 0; mt < 2; mt++) {
        int r0 = mw + mt * 16 + g, r1 = r0 + 8;
        size_t o0 = (((size_t)(b0 + (r0 >> 6)) * 64) + (r0 & 63)) * 128;
        size_t o1 = (((size_t)(b0 + (r1 >> 6)) * 64) + (r1 & 63)) * 128;
#pragma unroll
        for (int nt = 0; nt < 4; nt++) {
            int c0 = nw + nt * 8 + t2 * 2;
            float v00 = fmaxf(acc[mt][nt][0] + bb[nt].x, 0.f);
            float v01 = fmaxf(acc[mt][nt][1] + bb[nt].y, 0.f);
            float v10 = fmaxf(acc[mt][nt][2] + bb[nt].x, 0.f);
            float v11 = fmaxf(acc[mt][nt][3] + bb[nt].y, 0.f);
            __nv_bfloat162 h0, l0, h1, l1;
            split_bf(v00, h0.x, l0.x); split_bf(v01, h0.y, l0.y);
            split_bf(v10, h1.x, l1.x); split_bf(v11, h1.y, l1.y);
            *(__nv_bfloat162*)&g_a2h[o0 + c0] = h0;
            *(__nv_bfloat162*)&g_a2l[o0 + c0] = l0;
            *(__nv_bfloat162*)&g_a2h[o1 + c0] = h1;
            *(__nv_bfloat162*)&g_a2l[o1 + c0] = l1;
        }
    }
}

// ---------- conv3: 8 images/block x 128 co, K=1152 ----------
__global__ __launch_bounds__(512, 2) void conv3_k(const float* __restrict__ bias) {
    extern __shared__ __nv_bfloat16 smem_bf[];
    __nv_bfloat16* base[4] = {smem_bf, smem_bf + 10240, smem_bf + 20480, smem_bf + 30720};
    int tid = threadIdx.x;
    int b0 = blockIdx.x * 8;
    int cob = blockIdx.y * 128;
    int lane = tid & 31, wrp = tid >> 5;
    int g = lane >> 2, t2 = lane & 3;
    int mw = (wrp & 3) * 32, nw = (wrp >> 2) * 32;
    int rA = (lane & 7) + ((lane >> 3) & 1) * 8, kA = (lane >> 4) * 8;
    int nB = (lane >> 4) * 8 + (lane & 7), kB = ((lane >> 3) & 1) * 8;
    float acc[2][4][4];
#pragma unroll
    for (int mt = 0; mt < 2; mt++)
#pragma unroll
        for (int nt = 0; nt < 4; nt++)
#pragma unroll
            for (int i = 0; i < 4; i++) acc[mt][nt][i] = 0.f;

    auto stage = [&](int ch, int buf) {
        int tap = ch >> 2, ci0 = (ch & 3) * 32;
        int kh = tap / 3, kw = tap - kh * 3;
#pragma unroll
        for (int l = 0; l < 4; l++) {
            int gi = tid + 512 * l;
            int arr = gi >> 9;
            int rem = gi & 511;
            int row = rem >> 2, q = rem & 3;
            __nv_bfloat16* dst = base[arr] + buf * 5120 + row * 40 + q * 8;
            if (arr < 2) {
                int img = row >> 4, pos = row & 15;
                int oh = pos >> 2, ow = pos & 3;
                int ih = oh * 2 + kh - 1, iw = ow * 2 + kw - 1;
                int ok = ((unsigned)ih < 8u && (unsigned)iw < 8u) ? 16 : 0;
                size_t si = ok ? ((((size_t)(b0 + img) * 64) + ih * 8 + iw) * 128 + ci0 + q * 8) : 0;
                cpa16z(dst, (arr ? g_a2l : g_a2h) + si, ok);
            } else {
                cpa16(dst, ((arr == 3) ? g_wB3l : g_wB3h)
                           + (size_t)tap * 32768 + (cob + row) * 128 + ci0 + q * 8);
            }
        }
        cpa_commit();
    };

    stage(0, 0);
    for (int ch = 0; ch < 36; ch++) {
        int cb = ch & 1;
        cpa_wait0();
        __syncthreads();
        if (ch + 1 < 36) stage(ch + 1, cb ^ 1);
        HMMA_STEP(cb, 0)
        HMMA_STEP(cb, 1)
    }
    float2 bb[4];
#pragma unroll
    for (int nt = 0; nt < 4; nt++) bb[nt] = *(const float2*)&bias[cob + nw + nt * 8 + t2 * 2];
#pragma unroll
    for (int mt = 0; mt < 2; mt++) {
        int r0 = mw + mt * 16 + g, r1 = r0 + 8;
        size_t o0 = (((size_t)(b0 + (r0 >> 4)) * 16) + (r0 & 15)) * 256 + cob;
        size_t o1 = (((size_t)(b0 + (r1 >> 4)) * 16) + (r1 & 15)) * 256 + cob;
#pragma unroll
        for (int nt = 0; nt < 4; nt++) {
            int c0 = nw + nt * 8 + t2 * 2;
            float v00 = fmaxf(acc[mt][nt][0] + bb[nt].x, 0.f);
            float v01 = fmaxf(acc[mt][nt][1] + bb[nt].y, 0.f);
            float v10 = fmaxf(acc[mt][nt][2] + bb[nt].x, 0.f);
            float v11 = fmaxf(acc[mt][nt][3] + bb[nt].y, 0.f);
            *(float2*)&g_fea[o0 + c0] = make_float2(v00, v01);
            *(float2*)&g_fea[o1 + c0] = make_float2(v10, v11);
            __nv_bfloat162 h0, l0, h1, l1;
            split_bf(v00, h0.x, l0.x); split_bf(v01, h0.y, l0.y);
            split_bf(v10, h1.x, l1.x); split_bf(v11, h1.y, l1.y);
            *(__nv_bfloat162*)&g_feah[o0 + c0] = h0;
            *(__nv_bfloat162*)&g_feal[o0 + c0] = l0;
            *(__nv_bfloat162*)&g_feah[o1 + c0] = h1;
            *(__nv_bfloat162*)&g_feal[o1 + c0] = l1;
        }
    }
}

// ---------- code norms ----------
__global__ void codenorm_k(const float* __restrict__ c0, const float* __restrict__ c1) {
    int c = blockIdx.x * 256 + threadIdx.x;
    const float* cp = (c < 512) ? c0 + (size_t)c * 256 : c1 + (size_t)(c - 512) * 256;
    float s = 0.f;
    for (int k = 0; k < 256; k += 4) {
        float4 v = *(const float4*)&cp[k];
        s += v.x * v.x + v.y * v.y + v.z * v.z + v.w * v.w;
    }
    g_cn[c] = s;
}

// ---------- VQ: 128 rows/block x 128-code tiles, K=256 ----------
__global__ __launch_bounds__(512, 2) void vq_k(const int* __restrict__ idxp) {
    extern __shared__ __nv_bfloat16 smem_bf[];
    __nv_bfloat16* base[4] = {smem_bf, smem_bf + 10240, smem_bf + 20480, smem_bf + 30720};
    int tid = threadIdx.x;
    int rowbase = blockIdx.x * 128;
    int lane = tid & 31, wrp = tid >> 5;
    int g = lane >> 2, t2 = lane & 3;
    int mw = (wrp & 3) * 32, nw = (wrp >> 2) * 32;
    int rA = (lane & 7) + ((lane >> 3) & 1) * 8, kA = (lane >> 4) * 8;
    int nB = (lane >> 4) * 8 + (lane & 7), kB = ((lane >> 3) & 1) * 8;
    int Kc = (idxp[0] == 0) ? 512 : 1024;
    int total = (Kc >> 7) * 8;               // tile = cc>>3, kc = cc&7
    float bv[4]; int bi[4];
#pragma unroll
    for (int i = 0; i < 4; i++) { bv[i] = 1e30f; bi[i] = 0; }
    float acc[2][4][4];
#pragma unroll
    for (int mt = 0; mt < 2; mt++)
#pragma unroll
        for (int nt = 0; nt < 4; nt++)
#pragma unroll
            for (int i = 0; i < 4; i++) acc[mt][nt][i] = 0.f;

    auto stage = [&](int cc, int buf) {
        int tile = cc >> 3, kc = cc & 7;
#pragma unroll
        for (int l = 0; l < 4; l++) {
            int gi = tid + 512 * l;
            int arr = gi >> 9;
            int rem = gi & 511;
            int row = rem >> 2, q = rem & 3;
            __nv_bfloat16* dst = base[arr] + buf * 5120 + row * 40 + q * 8;
            const __nv_bfloat16* src;
            if (arr < 2)
                src = (arr ? g_feal : g_feah) + (size_t)(rowbase + row) * 256 + kc * 32 + q * 8;
            else
                src = ((arr == 3) ? g_cdl : g_cdh) + (size_t)(tile * 128 + row) * 256 + kc * 32 + q * 8;
            cpa16(dst, src);
        }
        cpa_commit();
    };

    stage(0, 0);
    for (int cc = 0; cc < total; cc++) {
        int cb = cc & 1;
        cpa_wait0();
        __syncthreads();
        if (cc + 1 < total) stage(cc + 1, cb ^ 1);
        HMMA_STEP(cb, 0)
        HMMA_STEP(cb, 1)
        if ((cc & 7) == 7) {
            int tile = cc >> 3;
#pragma unroll
            for (int nt = 0; nt < 4; nt++) {
                int c0 = tile * 128 + nw + nt * 8 + t2 * 2;
                float cn0 = g_cn[c0], cn1 = g_cn[c0 + 1];
#pragma unroll
                for (int mt = 0; mt < 2; mt++) {
                    float d00 = cn0 - 2.f * acc[mt][nt][0];
                    float d01 = cn1 - 2.f * acc[mt][nt][1];
                    float d10 = cn0 - 2.f * acc[mt][nt][2];
                    float d11 = cn1 - 2.f * acc[mt][nt][3];
                    int b0i = mt * 2, b1i = mt * 2 + 1;
                    if (d00 < bv[b0i]) { bv[b0i] = d00; bi[b0i] = c0; }
                    if (d01 < bv[b0i]) { bv[b0i] = d01; bi[b0i] = c0 + 1; }
                    if (d10 < bv[b1i]) { bv[b1i] = d10; bi[b1i] = c0; }
                    if (d11 < bv[b1i]) { bv[b1i] = d11; bi[b1i] = c0 + 1; }
                }
            }
#pragma unroll
            for (int mt = 0; mt < 2; mt++)
#pragma unroll
                for (int nt = 0; nt < 4; nt++)
#pragma unroll
                    for (int i = 0; i < 4; i++) acc[mt][nt][i] = 0.f;
        }
    }
    __syncthreads();
    float (*sbv)[16] = (float(*)[16])smem_bf;
    int   (*sbi)[16] = (int(*)[16])(smem_bf + 4096);
    int qidx = (wrp >> 2) * 4 + t2;
#pragma unroll
    for (int mt = 0; mt < 2; mt++) {
        int r0 = mw + mt * 16 + g, r1 = r0 + 8;
        sbv[r0][qidx] = bv[mt * 2];     sbi[r0][qidx] = bi[mt * 2];
        sbv[r1][qidx] = bv[mt * 2 + 1]; sbi[r1][qidx] = bi[mt * 2 + 1];
    }
    __syncthreads();
    if (tid < 128) {
        float v = sbv[tid][0]; int ii = sbi[tid][0];
#pragma unroll
        for (int q = 1; q < 16; q++) {
            float v2 = sbv[tid][q]; int i2 = sbi[tid][q];
            if (v2 < v || (v2 == v && i2 < ii)) { v = v2; ii = i2; }
        }
        g_eidx[rowbase + tid] = ii;
    }
}

// ---------- ptab via HMMA: P[pos] = codes @ fc1w_pos^T ----------
__global__ __launch_bounds__(512, 2) void ptab_k() {
    extern __shared__ __nv_bfloat16 smem_bf[];
    __nv_bfloat16* base[4] = {smem_bf, smem_bf + 10240, smem_bf + 20480, smem_bf + 30720};
    int tid = threadIdx.x;
    int cbb = blockIdx.x * 128;
    int nbb = blockIdx.y * 128;
    int pos = blockIdx.z;
    int lane = tid & 31, wrp = tid >> 5;
    int g = lane >> 2, t2 = lane & 3;
    int mw = (wrp & 3) * 32, nw = (wrp >> 2) * 32;
    int rA = (lane & 7) + ((lane >> 3) & 1) * 8, kA = (lane >> 4) * 8;
    int nB = (lane >> 4) * 8 + (lane & 7), kB = ((lane >> 3) & 1) * 8;
    float acc[2][4][4];
#pragma unroll
    for (int mt = 0; mt < 2; mt++)
#pragma unroll
        for (int nt = 0; nt < 4; nt++)
#pragma unroll
            for (int i = 0; i < 4; i++) acc[mt][nt][i] = 0.f;

    auto stage = [&](int kc, int buf) {
#pragma unroll
        for (int l = 0; l < 4; l++) {
            int gi = tid + 512 * l;
            int arr = gi >> 9;
            int rem = gi & 511;
            int row = rem >> 2, q = rem & 3;
            __nv_bfloat16* dst = base[arr] + buf * 5120 + row * 40 + q * 8;
            const __nv_bfloat16* src;
            if (arr < 2)
                src = (arr ? g_cdl : g_cdh) + (size_t)(cbb + row) * 256 + kc * 32 + q * 8;
            else
                src = ((arr == 3) ? g_wbl : g_wbh)
                      + ((size_t)pos * 512 + nbb + row) * 256 + kc * 32 + q * 8;
            cpa16(dst, src);
        }
        cpa_commit();
    };

    stage(0, 0);
    for (int kc = 0; kc < 8; kc++) {
        int cb = kc & 1;
        cpa_wait0();
        __syncthreads();
        if (kc + 1 < 8) stage(kc + 1, cb ^ 1);
        HMMA_STEP(cb, 0)
        HMMA_STEP(cb, 1)
    }
#pragma unroll
    for (int mt = 0; mt < 2; mt++) {
        int r0 = mw + mt * 16 + g, r1 = r0 + 8;
        size_t o0 = ((size_t)pos * 1024 + cbb + r0) * 512 + nbb;
        size_t o1 = ((size_t)pos * 1024 + cbb + r1) * 512 + nbb;
#pragma unroll
        for (int nt = 0; nt < 4; nt++) {
            int c0 = nw + nt * 8 + t2 * 2;
            *(float2*)&g_P[o0 + c0] = make_float2(acc[mt][nt][0], acc[mt][nt][1]);
            *(float2*)&g_P[o1 + c0] = make_float2(acc[mt][nt][2], acc[mt][nt][3]);
        }
    }
}

__global__ void zero_hist_k() { g_hist[threadIdx.x] = 0; }

// ---------- loss partials + histogram ----------
__global__ void loss_hist_k(const float* __restrict__ c0, const float* __restrict__ c1) {
    __shared__ float red[256];
    int row = blockIdx.x * 256 + threadIdx.x;
    int e = g_eidx[row];
    atomicAdd(&g_hist[e], 1);
    const float* cp = (e < 512) ? c0 + (size_t)e * 256 : c1 + (size_t)(e - 512) * 256;
    const float* f = g_fea + (size_t)row * 256;
    float s = 0.f;
    for (int k = 0; k < 256; k += 4) {
        float4 q = *(const float4*)&cp[k];
        float4 fv = *(const float4*)&f[k];
        float a = q.x - fv.x, b = q.y - fv.y, c = q.z - fv.z, d = q.w - fv.w;
        s += a * a + b * b + c * c + d * d;
    }
    red[threadIdx.x] = s;
    __syncthreads();
    for (int st = 128; st; st >>= 1) {
        if (threadIdx.x < st) red[threadIdx.x] += red[threadIdx.x + st];
        __syncthreads();
    }
    if (threadIdx.x == 0) g_losspart[blockIdx.x] = red[0];
}

// ---------- h = gelu(sum_pos P + b1) ----------
__global__ __launch_bounds__(512) void hgs_k(const float* __restrict__ fb) {
    __shared__ int se[16];
    int b = blockIdx.x, tid = threadIdx.x;
    if (tid < 16) se[tid] = g_eidx[b * 16 + tid];
    __syncthreads();
    float acc = fb[tid];
#pragma unroll
    for (int p = 0; p < 16; p++) acc += g_P[((size_t)p * 1024 + se[p]) * 512 + tid];
    g_h[(size_t)b * 512 + tid] = gelu_t(acc);
}

// ---------- fc2 ----------
__global__ __launch_bounds__(256) void fc2_k(const float* __restrict__ w,
                                             const float* __restrict__ bias,
                                             float* __restrict__ out) {
    __shared__ float sw[10][512];
    __shared__ float sb[10];
    int tid = threadIdx.x;
    for (int i = tid; i < 5120; i += 256) sw[i >> 9][i & 511] = w[i];
    if (tid < 10) sb[tid] = bias[tid];
    __syncthreads();
    int warp = tid >> 5, lane = tid & 31;
    int bimg = blockIdx.x * 8 + warp;
    const float* hr = g_h + (size_t)bimg * 512;
    float acc[10];
#pragma unroll
    for (int m = 0; m < 10; m++) acc[m] = 0.f;
    for (int k = 0; k < 16; k++) {
        float hv = hr[lane + 32 * k];
#pragma unroll
        for (int m = 0; m < 10; m++) acc[m] = fmaf(hv, sw[m][lane + 32 * k], acc[m]);
    }
#pragma unroll
    for (int off = 16; off; off >>= 1)
#pragma unroll
        for (int m = 0; m < 10; m++) acc[m] += __shfl_xor_sync(0xFFFFFFFFu, acc[m], off);
    if (lane < 10) out[(size_t)bimg * 10 + lane] = acc[lane] + sb[lane];
}

// ---------- loss + perplexity ----------
__global__ void losspp_k(float* __restrict__ dout, int osz) {
    __shared__ float red[256];
    int tid = threadIdx.x;
    red[tid] = g_losspart[tid];
    __syncthreads();
    for (int st = 128; st; st >>= 1) {
        if (tid < st) red[tid] += red[tid + st];
        __syncthreads();
    }
    float loss = 1.25f * red[0] / 16777216.0f;
    __syncthreads();
    float s = 0.f;
    for (int i = tid; i < 1024; i += 256) {
        float p = (float)g_hist[i] / 65536.0f;
        if (p > 0.f) s += p * logf(p + 1e-10f);
    }
    red[tid] = s;
    __syncthreads();
    for (int st = 128; st; st >>= 1) {
        if (tid < st) red[tid] += red[tid + st];
        __syncthreads();
    }
    if (tid == 0) { dout[osz - 2] = loss; dout[osz - 1] = expf(-red[0]); }
}

extern "C" void kernel_launch(void* const* d_in, const int* in_sizes, int n_in,
                              void* d_out, int out_size) {
    const float* x     = (const float*)d_in[0];
    const float* w1    = (const float*)d_in[1];
    const float* b1    = (const float*)d_in[2];
    const float* w2    = (const float*)d_in[3];
    const float* b2    = (const float*)d_in[4];
    const float* w3    = (const float*)d_in[5];
    const float* b3    = (const float*)d_in[6];
    const float* code0 = (const float*)d_in[7];
    const float* code1 = (const float*)d_in[8];
    const float* fc1w  = (const float*)d_in[9];
    const float* fc1b  = (const float*)d_in[10];
    const float* fc2w  = (const float*)d_in[11];
    const float* fc2b  = (const float*)d_in[12];
    const int*   idxp  = (const int*)d_in[13];
    float* out = (float*)d_out;

    cudaFuncSetAttribute(conv2_k, cudaFuncAttributeMaxDynamicSharedMemorySize, 81920);
    cudaFuncSetAttribute(conv3_k, cudaFuncAttributeMaxDynamicSharedMemorySize, 81920);
    cudaFuncSetAttribute(vq_k,    cudaFuncAttributeMaxDynamicSharedMemorySize, 81920);
    cudaFuncSetAttribute(ptab_k,  cudaFuncAttributeMaxDynamicSharedMemorySize, 81920);

    // conv2_k stays at our launch #3 (ncu -s 5 lands there after 2 harness launches).
    conv1_k<<<4096, 256>>>(x, w1, b1);                    // 0
    cvt_w2_k<<<9, 256>>>(w2);                             // 1
    cvt_w3_k<<<9, 256>>>(w3);                             // 2
    conv2_k<<<2048, 512, 81920>>>(b2);                    // 3
    conv3_k<<<dim3(512, 2), 512, 81920>>>(b3);            // 4
    cvt_cd_k<<<1024, 256>>>(code0, code1);                // 5
    codenorm_k<<<4, 256>>>(code0, code1);                 // 6
    vq_k<<<512, 512, 81920>>>(idxp);                      // 7
    zero_hist_k<<<1, 1024>>>();                           // 8
    loss_hist_k<<<256, 256>>>(code0, code1);              // 9
    cvt_wb_k<<<512, 256>>>(fc1w);                         // 10
    ptab_k<<<dim3(8, 4, 16), 512, 81920>>>();             // 11
    hgs_k<<<4096, 512>>>(fc1b);                           // 12
    fc2_k<<<512, 256>>>(fc2w, fc2b, out);                 // 13
    losspp_k<<<1, 256>>>(out, out_size);                  // 14
}